// round 15
// baseline (speedup 1.0000x reference)
#include <cuda_runtime.h>
#include <math.h>
#include <stdint.h>

#define ONE_THIRD2  (2.0f / 3.0f)
#define FOUR_THIRDS (4.0f / 3.0f)
#define LCAP        192
#define ZBLOCKS     12288

// Scratch (no allocations allowed)
__device__ float g_part[4096];   // per-block partial sums of NN distance

// ---------------------------------------------------------------------------
// Cubic spline weight (matches reference piecewise formula + support mask)
// ---------------------------------------------------------------------------
__device__ __forceinline__ float cubic_w(float q) {
    float w;
    if (q <= 0.5f) w = ONE_THIRD2 + 4.f * q * q * (q - 1.f);
    else           w = FOUR_THIRDS + q * (-4.f + q * (4.f - FOUR_THIRDS * q));
    return (q <= 1.f) ? w : 0.f;
}

// ===========================================================================
// Kernel A (fast path): block-role split.
//   blocks [0, mdblk)          : min_dist2 — NN distance, 2 nodes per warp
//                                sharing each float4 load (proven ~10us)
//   blocks [mdblk, mdblk+ZB)   : zero_fill — grid-stride float4 .wb stores
//                                (proven 28.4us @ 5 TB/s, DRAM 63%)
// The compute blocks hide entirely inside the bandwidth-bound window.
// ===========================================================================
__global__ __launch_bounds__(256) void fillA(const float2* __restrict__ nodes, int N,
                                             float* __restrict__ out, size_t total,
                                             int mdblk) {
    const int tid = threadIdx.x;

    if ((int)blockIdx.x < mdblk) {
        // ---------------- min_dist2 role ----------------
        __shared__ float s_d[8];
        const int lane = tid & 31;
        const int wid  = tid >> 5;
        const int half = N >> 1;
        const int N2   = N >> 1;             // float4 count
        const float4* n4 = (const float4*)nodes;

        const int i0 = blockIdx.x * 8 + wid;   // in [0, N/2)
        const int i1 = i0 + half;
        const float2 xa = __ldg(&nodes[i0]);
        const float2 xb = __ldg(&nodes[i1]);

        float mA0 = 3.4e38f, mA1 = 3.4e38f, mB0 = 3.4e38f, mB1 = 3.4e38f;
        #pragma unroll 4
        for (int jj = lane; jj < N2; jj += 32) {
            const float4 v = __ldg(&n4[jj]);
            const int j0 = jj * 2, j1 = j0 + 1;
            float ax0 = xa.x - v.x, ay0 = xa.y - v.y;
            float ax1 = xa.x - v.z, ay1 = xa.y - v.w;
            float bx0 = xb.x - v.x, by0 = xb.y - v.y;
            float bx1 = xb.x - v.z, by1 = xb.y - v.w;
            float dA0 = fmaf(ax0, ax0, ay0 * ay0);
            float dA1 = fmaf(ax1, ax1, ay1 * ay1);
            float dB0 = fmaf(bx0, bx0, by0 * by0);
            float dB1 = fmaf(bx1, bx1, by1 * by1);
            if (j0 != i0) mA0 = fminf(mA0, dA0);
            if (j1 != i0) mA1 = fminf(mA1, dA1);
            if (j0 != i1) mB0 = fminf(mB0, dB0);
            if (j1 != i1) mB1 = fminf(mB1, dB1);
        }
        float mA = fminf(mA0, mA1);
        float mB = fminf(mB0, mB1);
        #pragma unroll
        for (int o = 16; o; o >>= 1) {
            mA = fminf(mA, __shfl_xor_sync(0xffffffffu, mA, o));
            mB = fminf(mB, __shfl_xor_sync(0xffffffffu, mB, o));
        }
        if (lane == 0) s_d[wid] = sqrtf(mA) + sqrtf(mB);
        __syncthreads();
        if (tid == 0) {
            float s = 0.f;
            #pragma unroll
            for (int w = 0; w < 8; w++) s += s_d[w];
            g_part[blockIdx.x] = s;
        }
    } else {
        // ---------------- zero_fill role ----------------
        const size_t nv = total >> 2;
        float4* o4 = (float4*)out;
        const float4 z = make_float4(0.f, 0.f, 0.f, 0.f);
        const int zb = (int)blockIdx.x - mdblk;
        const size_t nzb = (size_t)(gridDim.x - mdblk);
        const size_t stride = nzb * 256;
        for (size_t i = (size_t)zb * 256 + tid; i < nv; i += stride)
            o4[i] = z;
        if (zb == 0 && tid < (int)(total & 3))
            out[(nv << 2) + tid] = 0.f;
    }
}

// ===========================================================================
// Kernel B (fast path): moments + inversion + sparse scatter. Warp per query.
// Per-warp deterministic dilation reduce (identical order in every warp),
// float4 moment sweep + in-support index list, lane-0 fp64 adjugate
// inversion, then overwrite only the ~21 nonzero entries per plane
// (zeros already laid down by kernel A; stream order guarantees visibility).
// ===========================================================================
__global__ __launch_bounds__(256) void momentsB(const float2* __restrict__ x,
                                                const float2* __restrict__ nodes,
                                                float* __restrict__ out,
                                                int B, int N, int mdblk) {
    __shared__ int s_list[8][LCAP];
    __shared__ int s_cnt[8];

    const int tid  = threadIdx.x;
    const int lane = tid & 31;
    const int wid  = tid >> 5;

    // per-warp deterministic dilation (fixed order, identical in all warps)
    float s = 0.f;
    for (int i = lane; i < mdblk; i += 32) s += g_part[i];
    #pragma unroll
    for (int o = 16; o; o >>= 1) s += __shfl_xor_sync(0xffffffffu, s, o);
    const float dil     = 2.5f * (s / (float)N);
    const float inv_dil = 1.f / dil;
    const float dil2    = dil * dil;

    const int qi = blockIdx.x * 8 + wid;
    if (qi >= B) return;
    const float2 qv = __ldg(&x[qi]);
    if (lane == 0) s_cnt[wid] = 0;
    __syncwarp();

    // float4 moment sweep + in-support list (order-independent)
    float a0 = 0.f, a1 = 0.f, a2 = 0.f, a3 = 0.f, a4 = 0.f, a5 = 0.f;
    {
        const float4* n4 = (const float4*)nodes;
        const int N2 = N >> 1;
        for (int jj = lane; jj < N2; jj += 32) {
            const float4 v = __ldg(&n4[jj]);
            {
                float dx = qv.x - v.x, dy = qv.y - v.y;
                float d2 = dx * dx + dy * dy + 1e-10f;
                if (d2 <= dil2) {
                    float w = cubic_w(sqrtf(d2) * inv_dil);
                    a0 += w;
                    a1 = fmaf(w, dx, a1); a2 = fmaf(w, dy, a2);
                    a3 = fmaf(w * dx, dx, a3); a4 = fmaf(w * dx, dy, a4); a5 = fmaf(w * dy, dy, a5);
                    int p = atomicAdd(&s_cnt[wid], 1);
                    if (p < LCAP) s_list[wid][p] = 2 * jj;
                }
            }
            {
                float dx = qv.x - v.z, dy = qv.y - v.w;
                float d2 = dx * dx + dy * dy + 1e-10f;
                if (d2 <= dil2) {
                    float w = cubic_w(sqrtf(d2) * inv_dil);
                    a0 += w;
                    a1 = fmaf(w, dx, a1); a2 = fmaf(w, dy, a2);
                    a3 = fmaf(w * dx, dx, a3); a4 = fmaf(w * dx, dy, a4); a5 = fmaf(w * dy, dy, a5);
                    int p = atomicAdd(&s_cnt[wid], 1);
                    if (p < LCAP) s_list[wid][p] = 2 * jj + 1;
                }
            }
        }
    }
    #pragma unroll
    for (int o = 16; o; o >>= 1) {
        a0 += __shfl_xor_sync(0xffffffffu, a0, o);
        a1 += __shfl_xor_sync(0xffffffffu, a1, o);
        a2 += __shfl_xor_sync(0xffffffffu, a2, o);
        a3 += __shfl_xor_sync(0xffffffffu, a3, o);
        a4 += __shfl_xor_sync(0xffffffffu, a4, o);
        a5 += __shfl_xor_sync(0xffffffffu, a5, o);
    }

    // fp64 adjugate inversion (lane 0) + shuffle broadcast
    float i00, i01, i02, i11, i12, i22;
    if (lane == 0) {
        double a = (double)a0 + 1e-5, bb = (double)a1, c = (double)a2;
        double d = (double)a3 + 1e-5, e  = (double)a4, f = (double)a5 + 1e-5;
        double c00 = d * f - e * e;
        double c01 = c * e - bb * f;
        double c02 = bb * e - c * d;
        double det = a * c00 + bb * c01 + c * c02;
        double id  = 1.0 / det;
        i00 = (float)(c00 * id);
        i01 = (float)(c01 * id);
        i02 = (float)(c02 * id);
        i11 = (float)((a * f - c * c) * id);
        i12 = (float)((bb * c - a * e) * id);
        i22 = (float)((a * d - bb * bb) * id);
    }
    i00 = __shfl_sync(0xffffffffu, i00, 0);
    i01 = __shfl_sync(0xffffffffu, i01, 0);
    i02 = __shfl_sync(0xffffffffu, i02, 0);
    i11 = __shfl_sync(0xffffffffu, i11, 0);
    i12 = __shfl_sync(0xffffffffu, i12, 0);
    i22 = __shfl_sync(0xffffffffu, i22, 0);
    __syncwarp();

    const size_t BN = (size_t)B * (size_t)N;
    float* __restrict__ o0 = out + (size_t)qi * (size_t)N;
    float* __restrict__ o1 = o0 + BN;
    float* __restrict__ o2 = o1 + BN;
    const int cnt = s_cnt[wid];

    if (cnt <= LCAP) {
        for (int k = lane; k < cnt; k += 32) {
            const int n = s_list[wid][k];
            const float2 nd = __ldg(&nodes[n]);
            float dx = qv.x - nd.x, dy = qv.y - nd.y;
            float d2 = dx * dx + dy * dy + 1e-10f;
            float w = cubic_w(sqrtf(d2) * inv_dil);
            o0[n] =  w * (i00 + i01 * dx + i02 * dy);
            o1[n] = -(w * (i01 + i11 * dx + i12 * dy));
            o2[n] = -(w * (i02 + i12 * dx + i22 * dy));
        }
    } else {
        for (int n = lane; n < N; n += 32) {
            const float2 nd = __ldg(&nodes[n]);
            float dx = qv.x - nd.x, dy = qv.y - nd.y;
            float d2 = dx * dx + dy * dy + 1e-10f;
            if (d2 <= dil2) {
                float w = cubic_w(sqrtf(d2) * inv_dil);
                o0[n] =  w * (i00 + i01 * dx + i02 * dy);
                o1[n] = -(w * (i01 + i11 * dx + i12 * dy));
                o2[n] = -(w * (i02 + i12 * dx + i22 * dy));
            }
        }
    }
}

// ===========================================================================
// GENERIC FALLBACK (any N) — R13 pipeline, known correct
// ===========================================================================

__global__ __launch_bounds__(256) void zero_fill(float* __restrict__ out, size_t total) {
    const size_t nv = total >> 2;
    float4* o4 = (float4*)out;
    const float4 z = make_float4(0.f, 0.f, 0.f, 0.f);
    const size_t stride = (size_t)gridDim.x * 256;
    for (size_t i = (size_t)blockIdx.x * 256 + threadIdx.x; i < nv; i += stride)
        o4[i] = z;
    if (blockIdx.x == 0 && threadIdx.x < (total & 3))
        out[(nv << 2) + threadIdx.x] = 0.f;
}

__global__ __launch_bounds__(256) void min_dist_kernel(const float2* __restrict__ nodes, int N) {
    __shared__ float s_d[8];
    const int tid  = threadIdx.x;
    const int lane = tid & 31;
    const int wid  = tid >> 5;
    float dsum = 0.f;
    for (int i = blockIdx.x * 8 + wid; i < N; i += gridDim.x * 8) {
        const float2 xi = __ldg(&nodes[i]);
        float m = 3.4e38f;
        for (int j = lane; j < N; j += 32) {
            const float2 nd = __ldg(&nodes[j]);
            float dx = xi.x - nd.x, dy = xi.y - nd.y;
            float d2 = fmaf(dx, dx, dy * dy);
            if (j != i) m = fminf(m, d2);
        }
        #pragma unroll
        for (int o = 16; o; o >>= 1) m = fminf(m, __shfl_xor_sync(0xffffffffu, m, o));
        if (lane == 0) dsum += sqrtf(m);
    }
    if (lane == 0) s_d[wid] = dsum;
    __syncthreads();
    if (tid == 0) {
        float t = 0.f;
        #pragma unroll
        for (int w = 0; w < 8; w++) t += s_d[w];
        g_part[blockIdx.x] = t;
    }
}

__global__ __launch_bounds__(256) void moments_scatter(const float2* __restrict__ x,
                                                       const float2* __restrict__ nodes,
                                                       float* __restrict__ out,
                                                       int B, int N, int nblk) {
    __shared__ float s_red[256];
    __shared__ int   s_list[8][LCAP];
    __shared__ int   s_cnt[8];
    __shared__ float s_p[2];
    const int tid  = threadIdx.x;
    const int lane = tid & 31;
    const int wid  = tid >> 5;
    {
        float t = 0.f;
        for (int i = tid; i < nblk; i += 256) t += g_part[i];
        s_red[tid] = t;
        __syncthreads();
        #pragma unroll
        for (int o = 128; o; o >>= 1) {
            if (tid < o) s_red[tid] += s_red[tid + o];
            __syncthreads();
        }
        if (tid == 0) {
            float dil = 2.5f * (s_red[0] / (float)N);
            s_p[0] = 1.f / dil;
            s_p[1] = dil * dil;
        }
        __syncthreads();
    }
    const float inv_dil = s_p[0];
    const float dil2    = s_p[1];
    const int qi = blockIdx.x * 8 + wid;
    if (qi >= B) return;
    const float2 qv = __ldg(&x[qi]);
    if (lane == 0) s_cnt[wid] = 0;
    __syncwarp();

    float a0 = 0.f, a1 = 0.f, a2 = 0.f, a3 = 0.f, a4 = 0.f, a5 = 0.f;
    for (int n = lane; n < N; n += 32) {
        const float2 nd = __ldg(&nodes[n]);
        float dx = qv.x - nd.x, dy = qv.y - nd.y;
        float d2 = dx * dx + dy * dy + 1e-10f;
        if (d2 <= dil2) {
            float w = cubic_w(sqrtf(d2) * inv_dil);
            a0 += w;
            a1 = fmaf(w, dx, a1); a2 = fmaf(w, dy, a2);
            a3 = fmaf(w * dx, dx, a3); a4 = fmaf(w * dx, dy, a4); a5 = fmaf(w * dy, dy, a5);
            int p = atomicAdd(&s_cnt[wid], 1);
            if (p < LCAP) s_list[wid][p] = n;
        }
    }
    #pragma unroll
    for (int o = 16; o; o >>= 1) {
        a0 += __shfl_xor_sync(0xffffffffu, a0, o);
        a1 += __shfl_xor_sync(0xffffffffu, a1, o);
        a2 += __shfl_xor_sync(0xffffffffu, a2, o);
        a3 += __shfl_xor_sync(0xffffffffu, a3, o);
        a4 += __shfl_xor_sync(0xffffffffu, a4, o);
        a5 += __shfl_xor_sync(0xffffffffu, a5, o);
    }
    float i00, i01, i02, i11, i12, i22;
    if (lane == 0) {
        double a = (double)a0 + 1e-5, bb = (double)a1, c = (double)a2;
        double d = (double)a3 + 1e-5, e  = (double)a4, f = (double)a5 + 1e-5;
        double c00 = d * f - e * e;
        double c01 = c * e - bb * f;
        double c02 = bb * e - c * d;
        double det = a * c00 + bb * c01 + c * c02;
        double id  = 1.0 / det;
        i00 = (float)(c00 * id); i01 = (float)(c01 * id); i02 = (float)(c02 * id);
        i11 = (float)((a * f - c * c) * id);
        i12 = (float)((bb * c - a * e) * id);
        i22 = (float)((a * d - bb * bb) * id);
    }
    i00 = __shfl_sync(0xffffffffu, i00, 0);
    i01 = __shfl_sync(0xffffffffu, i01, 0);
    i02 = __shfl_sync(0xffffffffu, i02, 0);
    i11 = __shfl_sync(0xffffffffu, i11, 0);
    i12 = __shfl_sync(0xffffffffu, i12, 0);
    i22 = __shfl_sync(0xffffffffu, i22, 0);
    __syncwarp();

    const size_t BN = (size_t)B * (size_t)N;
    float* __restrict__ o0 = out + (size_t)qi * (size_t)N;
    float* __restrict__ o1 = o0 + BN;
    float* __restrict__ o2 = o1 + BN;
    const int cnt = s_cnt[wid];
    if (cnt <= LCAP) {
        for (int k = lane; k < cnt; k += 32) {
            const int n = s_list[wid][k];
            const float2 nd = __ldg(&nodes[n]);
            float dx = qv.x - nd.x, dy = qv.y - nd.y;
            float d2 = dx * dx + dy * dy + 1e-10f;
            float w = cubic_w(sqrtf(d2) * inv_dil);
            o0[n] =  w * (i00 + i01 * dx + i02 * dy);
            o1[n] = -(w * (i01 + i11 * dx + i12 * dy));
            o2[n] = -(w * (i02 + i12 * dx + i22 * dy));
        }
    } else {
        for (int n = lane; n < N; n += 32) {
            const float2 nd = __ldg(&nodes[n]);
            float dx = qv.x - nd.x, dy = qv.y - nd.y;
            float d2 = dx * dx + dy * dy + 1e-10f;
            if (d2 <= dil2) {
                float w = cubic_w(sqrtf(d2) * inv_dil);
                o0[n] =  w * (i00 + i01 * dx + i02 * dy);
                o1[n] = -(w * (i01 + i11 * dx + i12 * dy));
                o2[n] = -(w * (i02 + i12 * dx + i22 * dy));
            }
        }
    }
}

// ---------------------------------------------------------------------------
// Launch: metadata order is {x, nodes}; output is [3, B, N] fp32.
// ---------------------------------------------------------------------------
extern "C" void kernel_launch(void* const* d_in, const int* in_sizes, int n_in,
                              void* d_out, int out_size) {
    const float2* x     = (const float2*)d_in[0];
    const float2* nodes = (const float2*)d_in[1];
    float* out = (float*)d_out;
    const int B = in_sizes[0] / 2;
    const int N = in_sizes[1] / 2;
    const size_t total = (size_t)out_size;

    if ((N & 15) == 0 && N / 16 <= 4096 && N >= 32) {
        // fast path: min_dist hides inside the zero-fill bandwidth window
        const int mdblk = N / 16;
        fillA<<<mdblk + ZBLOCKS, 256>>>(nodes, N, out, total, mdblk);
        momentsB<<<(B + 7) / 8, 256>>>(x, nodes, out, B, N, mdblk);
    } else {
        // generic fallback (proven correct)
        int zb = (int)((total / 4 + 255) / 256);
        if (zb > ZBLOCKS) zb = ZBLOCKS;
        zero_fill<<<zb, 256>>>(out, total);
        int nblk = (N + 7) / 8;
        if (nblk > 4096) nblk = 4096;
        min_dist_kernel<<<nblk, 256>>>(nodes, N);
        moments_scatter<<<(B + 7) / 8, 256>>>(x, nodes, out, B, N, nblk);
    }
}

// round 16
// speedup vs baseline: 1.3761x; 1.3761x over previous
#include <cuda_runtime.h>
#include <math.h>
#include <stdint.h>

#define ONE_THIRD2  (2.0f / 3.0f)
#define FOUR_THIRDS (4.0f / 3.0f)
#define LCAP        192
#define RMAX        4096

// Scratch (no allocations allowed)
__device__ float  g_part[4096];              // per-block NN-distance partial sums
__device__ float4 g_minv[2 * RMAX];          // per row: (i00,i01,i02,i11),(i12,i22,-,-)
__device__ int    g_cnt[RMAX];               // per row in-support count
__device__ float4 g_rec[(size_t)RMAX * LCAP]; // records: (n_bits, w, dx, dy)

// ---------------------------------------------------------------------------
__device__ __forceinline__ float cubic_w(float q) {
    float w;
    if (q <= 0.5f) w = ONE_THIRD2 + 4.f * q * q * (q - 1.f);
    else           w = FOUR_THIRDS + q * (-4.f + q * (4.f - FOUR_THIRDS * q));
    return (q <= 1.f) ? w : 0.f;
}

// deterministic per-warp dilation from g_part (identical order everywhere)
__device__ __forceinline__ void warp_dilation(int lane, int mdblk, int N,
                                              float& inv_dil, float& dil2) {
    float s = 0.f;
    for (int i = lane; i < mdblk; i += 32) s += g_part[i];
    #pragma unroll
    for (int o = 16; o; o >>= 1) s += __shfl_xor_sync(0xffffffffu, s, o);
    const float dil = 2.5f * (s / (float)N);
    inv_dil = 1.f / dil;
    dil2    = dil * dil;
}

// ===========================================================================
// K1: min_dist blocks [0, mdblk)  ∥  zero blocks [mdblk, gridDim) zeroing
//     float4 range [0, zsplit).
// ===========================================================================
__global__ __launch_bounds__(256) void k1_mind_zero(const float2* __restrict__ nodes, int N,
                                                    float* __restrict__ out, size_t zsplit,
                                                    int mdblk) {
    const int tid = threadIdx.x;
    if ((int)blockIdx.x < mdblk) {
        __shared__ float s_d[8];
        const int lane = tid & 31;
        const int wid  = tid >> 5;
        const int half = N >> 1;
        const int N2   = N >> 1;
        const float4* n4 = (const float4*)nodes;
        const int i0 = blockIdx.x * 8 + wid;
        const int i1 = i0 + half;
        const float2 xa = __ldg(&nodes[i0]);
        const float2 xb = __ldg(&nodes[i1]);
        float mA0 = 3.4e38f, mA1 = 3.4e38f, mB0 = 3.4e38f, mB1 = 3.4e38f;
        #pragma unroll 4
        for (int jj = lane; jj < N2; jj += 32) {
            const float4 v = __ldg(&n4[jj]);
            const int j0 = jj * 2, j1 = j0 + 1;
            float ax0 = xa.x - v.x, ay0 = xa.y - v.y;
            float ax1 = xa.x - v.z, ay1 = xa.y - v.w;
            float bx0 = xb.x - v.x, by0 = xb.y - v.y;
            float bx1 = xb.x - v.z, by1 = xb.y - v.w;
            float dA0 = fmaf(ax0, ax0, ay0 * ay0);
            float dA1 = fmaf(ax1, ax1, ay1 * ay1);
            float dB0 = fmaf(bx0, bx0, by0 * by0);
            float dB1 = fmaf(bx1, bx1, by1 * by1);
            if (j0 != i0) mA0 = fminf(mA0, dA0);
            if (j1 != i0) mA1 = fminf(mA1, dA1);
            if (j0 != i1) mB0 = fminf(mB0, dB0);
            if (j1 != i1) mB1 = fminf(mB1, dB1);
        }
        float mA = fminf(mA0, mA1);
        float mB = fminf(mB0, mB1);
        #pragma unroll
        for (int o = 16; o; o >>= 1) {
            mA = fminf(mA, __shfl_xor_sync(0xffffffffu, mA, o));
            mB = fminf(mB, __shfl_xor_sync(0xffffffffu, mB, o));
        }
        if (lane == 0) s_d[wid] = sqrtf(mA) + sqrtf(mB);
        __syncthreads();
        if (tid == 0) {
            float s = 0.f;
            #pragma unroll
            for (int w = 0; w < 8; w++) s += s_d[w];
            g_part[blockIdx.x] = s;
        }
    } else {
        float4* o4 = (float4*)out;
        const float4 z = make_float4(0.f, 0.f, 0.f, 0.f);
        const int zb = (int)blockIdx.x - mdblk;
        const size_t stride = (size_t)(gridDim.x - mdblk) * 256;
        for (size_t i = (size_t)zb * 256 + tid; i < zsplit; i += stride)
            o4[i] = z;
    }
}

// ===========================================================================
// K2: moments blocks [0, mblocks) — warp/row, MLP=4 batched sweep, records to
//     g_rec (NOT to out)  ∥  zero blocks zeroing float4 range [zsplit, nv)+tail.
// ===========================================================================
__global__ __launch_bounds__(256) void k2_mom_zero(const float2* __restrict__ x,
                                                   const float2* __restrict__ nodes,
                                                   float* __restrict__ out,
                                                   int B, int N, int mdblk, int mblocks,
                                                   size_t zsplit, size_t total) {
    const int tid = threadIdx.x;

    if ((int)blockIdx.x >= mblocks) {
        const size_t nv = total >> 2;
        float4* o4 = (float4*)out;
        const float4 z = make_float4(0.f, 0.f, 0.f, 0.f);
        const int zb = (int)blockIdx.x - mblocks;
        const size_t stride = (size_t)(gridDim.x - mblocks) * 256;
        for (size_t i = zsplit + (size_t)zb * 256 + tid; i < nv; i += stride)
            o4[i] = z;
        if (zb == 0 && tid < (int)(total & 3))
            out[(nv << 2) + tid] = 0.f;
        return;
    }

    __shared__ int s_cnt[8];
    const int lane = tid & 31;
    const int wid  = tid >> 5;

    float inv_dil, dil2;
    warp_dilation(lane, mdblk, N, inv_dil, dil2);

    const int qi = blockIdx.x * 8 + wid;
    if (qi >= B) return;
    const float2 qv = __ldg(&x[qi]);
    if (lane == 0) s_cnt[wid] = 0;
    __syncwarp();

    float a0 = 0.f, a1 = 0.f, a2 = 0.f, a3 = 0.f, a4 = 0.f, a5 = 0.f;

#define PROC(px, py, nidx)                                                      \
    {                                                                           \
        float dx = qv.x - (px), dy = qv.y - (py);                               \
        float d2 = dx * dx + dy * dy + 1e-10f;                                  \
        if (d2 <= dil2) {                                                       \
            float w = cubic_w(sqrtf(d2) * inv_dil);                             \
            a0 += w;                                                            \
            a1 = fmaf(w, dx, a1); a2 = fmaf(w, dy, a2);                         \
            a3 = fmaf(w * dx, dx, a3); a4 = fmaf(w * dx, dy, a4);               \
            a5 = fmaf(w * dy, dy, a5);                                          \
            int p = atomicAdd(&s_cnt[wid], 1);                                  \
            if (p < LCAP)                                                       \
                g_rec[(size_t)qi * LCAP + p] =                                  \
                    make_float4(__int_as_float(nidx), w, dx, dy);               \
        }                                                                       \
    }

    {
        const float4* n4 = (const float4*)nodes;
        const int N2 = N >> 1;
        int base = lane;
        // MLP=4: four independent LDG.128 in flight per iteration
        for (; base + 96 < N2; base += 128) {
            const float4 v0 = __ldg(&n4[base]);
            const float4 v1 = __ldg(&n4[base + 32]);
            const float4 v2 = __ldg(&n4[base + 64]);
            const float4 v3 = __ldg(&n4[base + 96]);
            PROC(v0.x, v0.y, 2 * base);            PROC(v0.z, v0.w, 2 * base + 1);
            PROC(v1.x, v1.y, 2 * (base + 32));     PROC(v1.z, v1.w, 2 * (base + 32) + 1);
            PROC(v2.x, v2.y, 2 * (base + 64));     PROC(v2.z, v2.w, 2 * (base + 64) + 1);
            PROC(v3.x, v3.y, 2 * (base + 96));     PROC(v3.z, v3.w, 2 * (base + 96) + 1);
        }
        for (; base < N2; base += 32) {
            const float4 v = __ldg(&n4[base]);
            PROC(v.x, v.y, 2 * base);              PROC(v.z, v.w, 2 * base + 1);
        }
    }
#undef PROC

    #pragma unroll
    for (int o = 16; o; o >>= 1) {
        a0 += __shfl_xor_sync(0xffffffffu, a0, o);
        a1 += __shfl_xor_sync(0xffffffffu, a1, o);
        a2 += __shfl_xor_sync(0xffffffffu, a2, o);
        a3 += __shfl_xor_sync(0xffffffffu, a3, o);
        a4 += __shfl_xor_sync(0xffffffffu, a4, o);
        a5 += __shfl_xor_sync(0xffffffffu, a5, o);
    }
    __syncwarp();
    if (lane == 0) {
        double a = (double)a0 + 1e-5, bb = (double)a1, c = (double)a2;
        double d = (double)a3 + 1e-5, e  = (double)a4, f = (double)a5 + 1e-5;
        double c00 = d * f - e * e;
        double c01 = c * e - bb * f;
        double c02 = bb * e - c * d;
        double det = a * c00 + bb * c01 + c * c02;
        double id  = 1.0 / det;
        g_minv[2 * qi]     = make_float4((float)(c00 * id), (float)(c01 * id),
                                         (float)(c02 * id), (float)((a * f - c * c) * id));
        g_minv[2 * qi + 1] = make_float4((float)((bb * c - a * e) * id),
                                         (float)((a * d - bb * bb) * id), 0.f, 0.f);
        g_cnt[qi] = s_cnt[wid];
    }
}

// ===========================================================================
// K3: scatter. Warp per row: apply ~cnt records x 3 planes. Fallback: full
//     row recompute if the record list overflowed (correct for any data).
// ===========================================================================
__global__ __launch_bounds__(256) void k3_scatter(const float2* __restrict__ x,
                                                  const float2* __restrict__ nodes,
                                                  float* __restrict__ out,
                                                  int B, int N, int mdblk) {
    const int tid  = threadIdx.x;
    const int lane = tid & 31;
    const int wid  = tid >> 5;
    const int qi = blockIdx.x * 8 + wid;
    if (qi >= B) return;

    const float4 m0 = g_minv[2 * qi];
    const float4 m1 = g_minv[2 * qi + 1];
    const float i00 = m0.x, i01 = m0.y, i02 = m0.z, i11 = m0.w;
    const float i12 = m1.x, i22 = m1.y;
    const int cnt = g_cnt[qi];

    const size_t BN = (size_t)B * (size_t)N;
    float* __restrict__ o0 = out + (size_t)qi * (size_t)N;
    float* __restrict__ o1 = o0 + BN;
    float* __restrict__ o2 = o1 + BN;

    if (cnt <= LCAP) {
        for (int k = lane; k < cnt; k += 32) {
            const float4 r = g_rec[(size_t)qi * LCAP + k];
            const int n = __float_as_int(r.x);
            const float w = r.y, dx = r.z, dy = r.w;
            o0[n] =  w * (i00 + i01 * dx + i02 * dy);
            o1[n] = -(w * (i01 + i11 * dx + i12 * dy));
            o2[n] = -(w * (i02 + i12 * dx + i22 * dy));
        }
    } else {
        float inv_dil, dil2;
        warp_dilation(lane, mdblk, N, inv_dil, dil2);
        const float2 qv = __ldg(&x[qi]);
        for (int n = lane; n < N; n += 32) {
            const float2 nd = __ldg(&nodes[n]);
            float dx = qv.x - nd.x, dy = qv.y - nd.y;
            float d2 = dx * dx + dy * dy + 1e-10f;
            if (d2 <= dil2) {
                float w = cubic_w(sqrtf(d2) * inv_dil);
                o0[n] =  w * (i00 + i01 * dx + i02 * dy);
                o1[n] = -(w * (i01 + i11 * dx + i12 * dy));
                o2[n] = -(w * (i02 + i12 * dx + i22 * dy));
            }
        }
    }
}

// ===========================================================================
// GENERIC FALLBACK (any N, B) — R13 pipeline, known correct
// ===========================================================================

__global__ __launch_bounds__(256) void zero_fill(float* __restrict__ out, size_t total) {
    const size_t nv = total >> 2;
    float4* o4 = (float4*)out;
    const float4 z = make_float4(0.f, 0.f, 0.f, 0.f);
    const size_t stride = (size_t)gridDim.x * 256;
    for (size_t i = (size_t)blockIdx.x * 256 + threadIdx.x; i < nv; i += stride)
        o4[i] = z;
    if (blockIdx.x == 0 && threadIdx.x < (total & 3))
        out[(nv << 2) + threadIdx.x] = 0.f;
}

__global__ __launch_bounds__(256) void min_dist_kernel(const float2* __restrict__ nodes, int N) {
    __shared__ float s_d[8];
    const int tid  = threadIdx.x;
    const int lane = tid & 31;
    const int wid  = tid >> 5;
    float dsum = 0.f;
    for (int i = blockIdx.x * 8 + wid; i < N; i += gridDim.x * 8) {
        const float2 xi = __ldg(&nodes[i]);
        float m = 3.4e38f;
        for (int j = lane; j < N; j += 32) {
            const float2 nd = __ldg(&nodes[j]);
            float dx = xi.x - nd.x, dy = xi.y - nd.y;
            float d2 = fmaf(dx, dx, dy * dy);
            if (j != i) m = fminf(m, d2);
        }
        #pragma unroll
        for (int o = 16; o; o >>= 1) m = fminf(m, __shfl_xor_sync(0xffffffffu, m, o));
        if (lane == 0) dsum += sqrtf(m);
    }
    if (lane == 0) s_d[wid] = dsum;
    __syncthreads();
    if (tid == 0) {
        float t = 0.f;
        #pragma unroll
        for (int w = 0; w < 8; w++) t += s_d[w];
        g_part[blockIdx.x] = t;
    }
}

__global__ __launch_bounds__(256) void moments_scatter(const float2* __restrict__ x,
                                                       const float2* __restrict__ nodes,
                                                       float* __restrict__ out,
                                                       int B, int N, int nblk) {
    __shared__ int s_list[8][LCAP];
    __shared__ int s_cnt[8];
    const int tid  = threadIdx.x;
    const int lane = tid & 31;
    const int wid  = tid >> 5;

    float inv_dil, dil2;
    warp_dilation(lane, nblk, N, inv_dil, dil2);

    const int qi = blockIdx.x * 8 + wid;
    if (qi >= B) return;
    const float2 qv = __ldg(&x[qi]);
    if (lane == 0) s_cnt[wid] = 0;
    __syncwarp();

    float a0 = 0.f, a1 = 0.f, a2 = 0.f, a3 = 0.f, a4 = 0.f, a5 = 0.f;
    for (int n = lane; n < N; n += 32) {
        const float2 nd = __ldg(&nodes[n]);
        float dx = qv.x - nd.x, dy = qv.y - nd.y;
        float d2 = dx * dx + dy * dy + 1e-10f;
        if (d2 <= dil2) {
            float w = cubic_w(sqrtf(d2) * inv_dil);
            a0 += w;
            a1 = fmaf(w, dx, a1); a2 = fmaf(w, dy, a2);
            a3 = fmaf(w * dx, dx, a3); a4 = fmaf(w * dx, dy, a4); a5 = fmaf(w * dy, dy, a5);
            int p = atomicAdd(&s_cnt[wid], 1);
            if (p < LCAP) s_list[wid][p] = n;
        }
    }
    #pragma unroll
    for (int o = 16; o; o >>= 1) {
        a0 += __shfl_xor_sync(0xffffffffu, a0, o);
        a1 += __shfl_xor_sync(0xffffffffu, a1, o);
        a2 += __shfl_xor_sync(0xffffffffu, a2, o);
        a3 += __shfl_xor_sync(0xffffffffu, a3, o);
        a4 += __shfl_xor_sync(0xffffffffu, a4, o);
        a5 += __shfl_xor_sync(0xffffffffu, a5, o);
    }
    float i00, i01, i02, i11, i12, i22;
    if (lane == 0) {
        double a = (double)a0 + 1e-5, bb = (double)a1, c = (double)a2;
        double d = (double)a3 + 1e-5, e  = (double)a4, f = (double)a5 + 1e-5;
        double c00 = d * f - e * e;
        double c01 = c * e - bb * f;
        double c02 = bb * e - c * d;
        double det = a * c00 + bb * c01 + c * c02;
        double id  = 1.0 / det;
        i00 = (float)(c00 * id); i01 = (float)(c01 * id); i02 = (float)(c02 * id);
        i11 = (float)((a * f - c * c) * id);
        i12 = (float)((bb * c - a * e) * id);
        i22 = (float)((a * d - bb * bb) * id);
    }
    i00 = __shfl_sync(0xffffffffu, i00, 0);
    i01 = __shfl_sync(0xffffffffu, i01, 0);
    i02 = __shfl_sync(0xffffffffu, i02, 0);
    i11 = __shfl_sync(0xffffffffu, i11, 0);
    i12 = __shfl_sync(0xffffffffu, i12, 0);
    i22 = __shfl_sync(0xffffffffu, i22, 0);
    __syncwarp();

    const size_t BN = (size_t)B * (size_t)N;
    float* __restrict__ o0 = out + (size_t)qi * (size_t)N;
    float* __restrict__ o1 = o0 + BN;
    float* __restrict__ o2 = o1 + BN;
    const int cnt = s_cnt[wid];
    if (cnt <= LCAP) {
        for (int k = lane; k < cnt; k += 32) {
            const int n = s_list[wid][k];
            const float2 nd = __ldg(&nodes[n]);
            float dx = qv.x - nd.x, dy = qv.y - nd.y;
            float d2 = dx * dx + dy * dy + 1e-10f;
            float w = cubic_w(sqrtf(d2) * inv_dil);
            o0[n] =  w * (i00 + i01 * dx + i02 * dy);
            o1[n] = -(w * (i01 + i11 * dx + i12 * dy));
            o2[n] = -(w * (i02 + i12 * dx + i22 * dy));
        }
    } else {
        for (int n = lane; n < N; n += 32) {
            const float2 nd = __ldg(&nodes[n]);
            float dx = qv.x - nd.x, dy = qv.y - nd.y;
            float d2 = dx * dx + dy * dy + 1e-10f;
            if (d2 <= dil2) {
                float w = cubic_w(sqrtf(d2) * inv_dil);
                o0[n] =  w * (i00 + i01 * dx + i02 * dy);
                o1[n] = -(w * (i01 + i11 * dx + i12 * dy));
                o2[n] = -(w * (i02 + i12 * dx + i22 * dy));
            }
        }
    }
}

// ---------------------------------------------------------------------------
// Launch: metadata order is {x, nodes}; output is [3, B, N] fp32.
// ---------------------------------------------------------------------------
extern "C" void kernel_launch(void* const* d_in, const int* in_sizes, int n_in,
                              void* d_out, int out_size) {
    const float2* x     = (const float2*)d_in[0];
    const float2* nodes = (const float2*)d_in[1];
    float* out = (float*)d_out;
    const int B = in_sizes[0] / 2;
    const int N = in_sizes[1] / 2;
    const size_t total = (size_t)out_size;

    if ((N & 15) == 0 && N / 16 <= 4096 && N >= 32 && B <= RMAX && B >= 1) {
        const int mdblk   = N / 16;
        const int mblocks = (B + 7) / 8;
        const size_t nv = total >> 2;
        const size_t zsplit = (nv * 45) / 100;            // K1 zeroes 45%, K2 55%
        k1_mind_zero<<<mdblk + 6144, 256>>>(nodes, N, out, zsplit, mdblk);
        k2_mom_zero<<<mblocks + 8192, 256>>>(x, nodes, out, B, N, mdblk, mblocks,
                                             zsplit, total);
        k3_scatter<<<mblocks, 256>>>(x, nodes, out, B, N, mdblk);
    } else {
        int zb = (int)((total / 4 + 255) / 256);
        if (zb > 12288) zb = 12288;
        zero_fill<<<zb, 256>>>(out, total);
        int nblk = (N + 7) / 8;
        if (nblk > 4096) nblk = 4096;
        min_dist_kernel<<<nblk, 256>>>(nodes, N);
        moments_scatter<<<(B + 7) / 8, 256>>>(x, nodes, out, B, N, nblk);
    }
}